// round 14
// baseline (speedup 1.0000x reference)
#include <cuda_runtime.h>
#include <cuda_fp16.h>
#include <math_constants.h>

// Problem dims fixed by setup_inputs(): N=100000, E=1600000, Fin=128, H1=2, Fh=32, Fout=128
#define NN 100000
#define EE 1600000
#define ET (EE + NN)

// ---------------- scratch (static device memory; no allocations allowed) ----------------
__device__ int   g_is64;
__device__ int   g_deg[NN];
__device__ int   g_rowptr[NN + 1];
__device__ int   g_cursor[NN];
__device__ int   g_blksum[128];
__device__ int   g_csr[ET];
__device__ __align__(16) __half g_h1h[NN * 64];   // layer1 pre-agg features (fp16 gather table)
__device__ __align__(8) float g_as1[NN * 2];      // alpha_src layer1 [N,H1]
__device__ __align__(8) float g_ad1[NN * 2];      // alpha_dst layer1
__device__ __align__(16) __half g_h1pf[NN * 64];  // relu(layer1 out) fp16 (layer2 gather table)
__device__ __align__(16) float  g_mn[NN * 64];    // normalized layer2 aggregate (pre-W2)
__device__ float g_as2[NN];
__device__ float g_ad2[NN];
__device__ __align__(8) float g_wa_src[64];       // W2 @ att_src2
__device__ __align__(8) float g_wa_dst[64];       // W2 @ att_dst2

__device__ __forceinline__ float lrelu(float x) { return x > 0.f ? x : 0.2f * x; }

__device__ __forceinline__ float wsum(float v) {
    #pragma unroll
    for (int o = 16; o; o >>= 1) v += __shfl_xor_sync(0xffffffffu, v, o);
    return v;
}

__device__ __forceinline__ unsigned h2_to_u(__half2 h) {
    union { __half2 h; unsigned u; } c; c.h = h; return c.u;
}

// ---- packed f32x2 helpers (Blackwell: fma.rn.f32x2 = 2 IEEE fp32 FMAs / instr) ----
__device__ __forceinline__ unsigned long long pk2(float lo, float hi) {
    unsigned long long r;
    asm("mov.b64 %0, {%1, %2};" : "=l"(r) : "f"(lo), "f"(hi));
    return r;
}
__device__ __forceinline__ unsigned long long dup2(float v) {
    unsigned long long r;
    asm("mov.b64 %0, {%1, %1};" : "=l"(r) : "f"(v));
    return r;
}
__device__ __forceinline__ void fma2(unsigned long long& acc, unsigned long long a, unsigned long long b) {
    asm("fma.rn.f32x2 %0, %1, %2, %0;" : "+l"(acc) : "l"(a), "l"(b));
}
__device__ __forceinline__ float2 unpk2(unsigned long long v) {
    float lo, hi;
    asm("mov.b64 {%0, %1}, %2;" : "=f"(lo), "=f"(hi) : "l"(v));
    return make_float2(lo, hi);
}

// ---------------- CSR build ----------------
// edge_index may arrive as int64 (reference dtype) or narrowed to int32 by the
// harness; probe once (int32 read as int64 -> fused indices >= N).
__global__ void k_init_deg(const void* ei, int N) {
    int i = blockIdx.x * blockDim.x + threadIdx.x;
    if (i < N) g_deg[i] = 1;  // self-loop
    if (i == 0) {
        const long long* p = (const long long*)ei;
        int ok = 1;
        #pragma unroll
        for (int k = 0; k < 16; k++) {
            long long v = p[k];
            if (v < 0 || v >= (long long)N) { ok = 0; break; }
        }
        g_is64 = ok;
    }
}

__global__ void k_count(const void* __restrict__ ei, int E, int N) {
    int i = blockIdx.x * blockDim.x + threadIdx.x;
    int e = i * 4;
    if (e >= E) return;
    int d[4];
    if (g_is64) {
        const long long* p = (const long long*)ei + E;
        longlong4 v = *(const longlong4*)&p[e];
        d[0] = (int)v.x; d[1] = (int)v.y; d[2] = (int)v.z; d[3] = (int)v.w;
    } else {
        const int* p = (const int*)ei + E;
        int4 v = *(const int4*)&p[e];
        d[0] = v.x; d[1] = v.y; d[2] = v.z; d[3] = v.w;
    }
    #pragma unroll
    for (int k = 0; k < 4; k++)
        if (e + k < E && (unsigned)d[k] < (unsigned)N) atomicAdd(&g_deg[d[k]], 1);
}

__global__ void k_scan1(int N) {
    __shared__ int sm[1024];
    int idx = blockIdx.x * 1024 + threadIdx.x;
    int v = (idx < N) ? g_deg[idx] : 0;
    sm[threadIdx.x] = v;
    __syncthreads();
    #pragma unroll
    for (int off = 1; off < 1024; off <<= 1) {
        int t = (threadIdx.x >= off) ? sm[threadIdx.x - off] : 0;
        __syncthreads();
        sm[threadIdx.x] += t;
        __syncthreads();
    }
    if (idx < N) g_rowptr[idx] = sm[threadIdx.x] - v;  // exclusive
    if (threadIdx.x == 1023) g_blksum[blockIdx.x] = sm[1023];
}

__global__ void k_scan3(int N, int total) {
    __shared__ int ws[4];
    __shared__ int sh_prefix;
    int b = blockIdx.x;
    int t = threadIdx.x;
    if (t < 128) {
        int lane = t & 31, w = t >> 5;
        int v = (t < b) ? g_blksum[t] : 0;   // b <= 97 < 128
        #pragma unroll
        for (int o = 16; o; o >>= 1) v += __shfl_xor_sync(0xffffffffu, v, o);
        if (lane == 0) ws[w] = v;
    }
    __syncthreads();
    if (t == 0) sh_prefix = ws[0] + ws[1] + ws[2] + ws[3];
    __syncthreads();
    int idx = b * 1024 + t;
    if (idx > N) return;
    if (idx == N) { g_rowptr[N] = total; return; }
    int v = g_rowptr[idx] + sh_prefix;
    g_rowptr[idx] = v;
    g_cursor[idx] = v;
}

__global__ void k_fill(const void* __restrict__ ei, int E, int N) {
    int i = blockIdx.x * blockDim.x + threadIdx.x;
    int E4 = (E + 3) >> 2;
    if (i < E4) {
        int e = i * 4;
        int s[4], d[4];
        if (g_is64) {
            const long long* ps = (const long long*)ei;
            const long long* pd = ps + E;
            longlong4 vs = *(const longlong4*)&ps[e];
            longlong4 vd = *(const longlong4*)&pd[e];
            s[0] = (int)vs.x; s[1] = (int)vs.y; s[2] = (int)vs.z; s[3] = (int)vs.w;
            d[0] = (int)vd.x; d[1] = (int)vd.y; d[2] = (int)vd.z; d[3] = (int)vd.w;
        } else {
            const int* ps = (const int*)ei;
            const int* pd = ps + E;
            int4 vs = *(const int4*)&ps[e];
            int4 vd = *(const int4*)&pd[e];
            s[0] = vs.x; s[1] = vs.y; s[2] = vs.z; s[3] = vs.w;
            d[0] = vd.x; d[1] = vd.y; d[2] = vd.z; d[3] = vd.w;
        }
        #pragma unroll
        for (int k = 0; k < 4; k++) {
            if (e + k >= E) break;
            if ((unsigned)d[k] >= (unsigned)N || (unsigned)s[k] >= (unsigned)N) continue;
            int pos = atomicAdd(&g_cursor[d[k]], 1);
            g_csr[pos] = s[k];
        }
    } else {
        int node = i - E4;
        if (node < N) {
            int pos = atomicAdd(&g_cursor[node], 1);
            g_csr[pos] = node;
        }
    }
}

// ---------------- prevec: wa_src = W2 @ att_src2, wa_dst = W2 @ att_dst2 ----------------
// W2 is [64,128] row-major; att vectors are [128]. 128 threads: t<64 -> src row t, t>=64 -> dst row t-64.
__global__ void k_prevec(const float* __restrict__ W2, const float* __restrict__ as,
                         const float* __restrict__ ad) {
    int t = threadIdx.x;
    int k = t & 63;
    const float* a = (t < 64) ? as : ad;
    const float4* w4 = (const float4*)&W2[k * 128];
    const float4* a4 = (const float4*)a;
    float acc = 0.f;
    #pragma unroll
    for (int j = 0; j < 32; j++) {
        float4 w = w4[j], v = a4[j];
        acc += w.x * v.x + w.y * v.y + w.z * v.z + w.w * v.w;
    }
    if (t < 64) g_wa_src[k] = acc; else g_wa_dst[k] = acc;
}

// ---------------- GEMM1: h1 = x @ W1 [128x64] -> fp16 table, fused alpha epilogue ----------------
__global__ void __launch_bounds__(256) k_gemm1(const float* __restrict__ x,
                                               const float* __restrict__ W1,
                                               const float* __restrict__ as,
                                               const float* __restrict__ ad, int N) {
    __shared__ float xs[128 * 68];   // 34.8 KB, transposed x tile
    int t = threadIdx.x;
    int tx = t & 15;                 // cols tx*4 .. tx*4+3
    int ty = t >> 4;                 // rows ty*4 .. ty*4+3
    int head = tx >> 3;
    int base = blockIdx.x * 64;

    float4 as4 = ((const float4*)as)[tx];
    float4 ad4 = ((const float4*)ad)[tx];

    for (int i = t; i < 64 * 128; i += 256) {
        int row = i >> 7, k = i & 127;
        int r = base + row;
        xs[k * 68 + row] = (r < N) ? x[r * 128 + k] : 0.f;
    }
    __syncthreads();

    unsigned long long acc2[4][2] = {};
    #pragma unroll 4
    for (int k = 0; k < 128; k++) {
        float4 w = __ldg((const float4*)&W1[k * 64 + tx * 4]);
        float4 xv = *(const float4*)&xs[k * 68 + ty * 4];
        unsigned long long w01 = pk2(w.x, w.y), w23 = pk2(w.z, w.w);
        unsigned long long x0 = dup2(xv.x), x1 = dup2(xv.y), x2 = dup2(xv.z), x3 = dup2(xv.w);
        fma2(acc2[0][0], x0, w01); fma2(acc2[0][1], x0, w23);
        fma2(acc2[1][0], x1, w01); fma2(acc2[1][1], x1, w23);
        fma2(acc2[2][0], x2, w01); fma2(acc2[2][1], x2, w23);
        fma2(acc2[3][0], x3, w01); fma2(acc2[3][1], x3, w23);
    }

    #pragma unroll
    for (int r = 0; r < 4; r++) {
        int row = base + ty * 4 + r;
        float2 h01 = unpk2(acc2[r][0]);
        float2 h23 = unpk2(acc2[r][1]);
        if (row < N) {
            uint2 pk;
            pk.x = h2_to_u(__floats2half2_rn(h01.x, h01.y));
            pk.y = h2_to_u(__floats2half2_rn(h23.x, h23.y));
            *(uint2*)&g_h1h[row * 64 + tx * 4] = pk;
        }
        float p = h01.x * as4.x + h01.y * as4.y + h23.x * as4.z + h23.y * as4.w;
        float q = h01.x * ad4.x + h01.y * ad4.y + h23.x * ad4.z + h23.y * ad4.w;
        #pragma unroll
        for (int o = 1; o <= 4; o <<= 1) {
            p += __shfl_xor_sync(0xffffffffu, p, o);
            q += __shfl_xor_sync(0xffffffffu, q, o);
        }
        if ((tx & 7) == 0 && row < N) {
            g_as1[row * 2 + head] = p;
            g_ad1[row * 2 + head] = q;
        }
    }
}

// ---------------- Layer1 aggregation: warp-coop two-phase -> h1p fp16 + layer2 logits ----------------
__global__ void k_agg1(const float* __restrict__ b1, int N) {
    int node = blockIdx.x * 8 + (threadIdx.x >> 5);
    if (node >= N) return;
    int lane = threadIdx.x & 31;
    int hsel = lane >> 4;
    int start = g_rowptr[node], end = g_rowptr[node + 1];
    float2 adp = *(const float2*)&g_ad1[node * 2];
    float2 acc = make_float2(0.f, 0.f);
    float s0 = 0.f, s1 = 0.f;
    for (int b = start; b < end; b += 32) {
        int i = b + lane;
        int src_l = 0; float ex0_l = 0.f, ex1_l = 0.f;
        if (i < end) {
            src_l = g_csr[i];
            float2 a = *(const float2*)&g_as1[src_l * 2];
            ex0_l = __expf(lrelu(a.x + adp.x));
            ex1_l = __expf(lrelu(a.y + adp.y));
        }
        s0 += ex0_l; s1 += ex1_l;
        int cnt = min(32, end - b);
        #pragma unroll 4
        for (int j = 0; j < cnt; j++) {
            int src  = __shfl_sync(0xffffffffu, src_l, j);
            float e0 = __shfl_sync(0xffffffffu, ex0_l, j);
            float e1 = __shfl_sync(0xffffffffu, ex1_l, j);
            float exh = hsel ? e1 : e0;
            float2 v = __half22float2(*(const __half2*)&g_h1h[src * 64 + lane * 2]);
            acc.x += exh * v.x; acc.y += exh * v.y;
        }
    }
    s0 = wsum(s0); s1 = wsum(s1);
    float inv = 1.f / (hsel ? s1 : s0);
    float2 bb = ((const float2*)b1)[lane];
    float2 o = make_float2(fmaxf(acc.x * inv + bb.x, 0.f), fmaxf(acc.y * inv + bb.y, 0.f));
    *(__half2*)&g_h1pf[node * 64 + lane * 2] = __floats2half2_rn(o.x, o.y);
    // layer2 attention logits: as2 = h1p . (W2@a_src), ad2 = h1p . (W2@a_dst)
    float2 was = *(const float2*)&g_wa_src[lane * 2];
    float2 wad = *(const float2*)&g_wa_dst[lane * 2];
    float ps = wsum(o.x * was.x + o.y * was.y);
    float pd = wsum(o.x * wad.x + o.y * wad.y);
    if (lane == 0) { g_as2[node] = ps; g_ad2[node] = pd; }
}

// ---------------- Layer2 aggregation in h1p space (64-dim, 128B/edge gather) ----------------
__global__ void k_agg2(int N) {
    int node = blockIdx.x * 8 + (threadIdx.x >> 5);
    if (node >= N) return;
    int lane = threadIdx.x & 31;
    int start = g_rowptr[node], end = g_rowptr[node + 1];
    float ad = g_ad2[node];
    float2 acc = make_float2(0.f, 0.f);
    float spart = 0.f;
    for (int b = start; b < end; b += 32) {
        int i = b + lane;
        int src_l = 0; float ex_l = 0.f;
        if (i < end) {
            src_l = g_csr[i];
            ex_l = __expf(lrelu(g_as2[src_l] + ad));
        }
        spart += ex_l;
        int cnt = min(32, end - b);
        #pragma unroll 4
        for (int j = 0; j < cnt; j++) {
            int src  = __shfl_sync(0xffffffffu, src_l, j);
            float ex = __shfl_sync(0xffffffffu, ex_l, j);
            float2 v = __half22float2(*(const __half2*)&g_h1pf[src * 64 + lane * 2]);
            acc.x += ex * v.x; acc.y += ex * v.y;
        }
    }
    float inv = 1.f / wsum(spart);
    *(float2*)&g_mn[node * 64 + lane * 2] = make_float2(acc.x * inv, acc.y * inv);
}

// ---------------- GEMM3: out = mn @ W2 + b2 [64x128], plain epilogue ----------------
__global__ void __launch_bounds__(256) k_gemm3(const float* __restrict__ W2,
                                               const float* __restrict__ b2,
                                               int N, float* __restrict__ out) {
    __shared__ float xs[64 * 68];    // 17.4 KB
    int t = threadIdx.x;
    int tx = t & 15;                 // cols tx*8 .. tx*8+7
    int ty = t >> 4;                 // rows ty*4 .. ty*4+3
    int base = blockIdx.x * 64;

    float4 bbA = __ldg((const float4*)&b2[tx * 8]);
    float4 bbB = __ldg((const float4*)&b2[tx * 8 + 4]);

    for (int i = t; i < 64 * 64; i += 256) {
        int row = i >> 6, k = i & 63;
        int r = base + row;
        xs[k * 68 + row] = (r < N) ? g_mn[r * 64 + k] : 0.f;
    }
    __syncthreads();

    unsigned long long acc2[4][4] = {};
    #pragma unroll 4
    for (int k = 0; k < 64; k++) {
        float4 wa = __ldg((const float4*)&W2[k * 128 + tx * 8]);
        float4 wb = __ldg((const float4*)&W2[k * 128 + tx * 8 + 4]);
        float4 xv = *(const float4*)&xs[k * 68 + ty * 4];
        unsigned long long wp[4] = { pk2(wa.x, wa.y), pk2(wa.z, wa.w),
                                     pk2(wb.x, wb.y), pk2(wb.z, wb.w) };
        unsigned long long xd[4] = { dup2(xv.x), dup2(xv.y), dup2(xv.z), dup2(xv.w) };
        #pragma unroll
        for (int r = 0; r < 4; r++) {
            fma2(acc2[r][0], xd[r], wp[0]);
            fma2(acc2[r][1], xd[r], wp[1]);
            fma2(acc2[r][2], xd[r], wp[2]);
            fma2(acc2[r][3], xd[r], wp[3]);
        }
    }

    #pragma unroll
    for (int r = 0; r < 4; r++) {
        int row = base + ty * 4 + r;
        if (row >= N) continue;
        float2 h0 = unpk2(acc2[r][0]), h1 = unpk2(acc2[r][1]);
        float2 h2 = unpk2(acc2[r][2]), h3 = unpk2(acc2[r][3]);
        float4 oA = make_float4(h0.x + bbA.x, h0.y + bbA.y, h1.x + bbA.z, h1.y + bbA.w);
        float4 oB = make_float4(h2.x + bbB.x, h2.y + bbB.y, h3.x + bbB.z, h3.y + bbB.w);
        *(float4*)&out[row * 128 + tx * 8]     = oA;
        *(float4*)&out[row * 128 + tx * 8 + 4] = oB;
    }
}

// ---------------- launch: fork CSR build onto a side stream, overlap with GEMM1 ----------------
extern "C" void kernel_launch(void* const* d_in, const int* in_sizes, int n_in,
                              void* d_out, int out_size) {
    const float* x   = (const float*)d_in[0];
    const void*  ei  = d_in[1];
    const float* W1  = (const float*)d_in[2];
    const float* as1 = (const float*)d_in[3];
    const float* ad1 = (const float*)d_in[4];
    const float* b1  = (const float*)d_in[5];
    const float* W2  = (const float*)d_in[6];
    const float* as2 = (const float*)d_in[7];
    const float* ad2 = (const float*)d_in[8];
    const float* b2  = (const float*)d_in[9];
    float* out = (float*)d_out;

    int N = in_sizes[0] / 128;
    int E = in_sizes[1] / 2;

    static cudaStream_t s2 = nullptr;
    static cudaEvent_t evFork = nullptr, evJoin = nullptr;
    if (!s2) {
        cudaStreamCreateWithFlags(&s2, cudaStreamNonBlocking);
        cudaEventCreateWithFlags(&evFork, cudaEventDisableTiming);
        cudaEventCreateWithFlags(&evJoin, cudaEventDisableTiming);
    }

    // fork: CSR build on s2
    cudaEventRecord(evFork, 0);
    cudaStreamWaitEvent(s2, evFork, 0);
    k_init_deg<<<(N + 255) / 256, 256, 0, s2>>>(ei, N);
    k_count<<<(E / 4 + 255) / 256, 256, 0, s2>>>(ei, E, N);
    int nb = (N + 1023) / 1024;
    k_scan1<<<nb, 1024, 0, s2>>>(N);
    k_scan3<<<nb, 1024, 0, s2>>>(N, E + N);
    {
        int E4 = (E + 3) / 4;
        k_fill<<<(E4 + N + 255) / 256, 256, 0, s2>>>(ei, E, N);
    }
    cudaEventRecord(evJoin, s2);

    // concurrent: prevec + GEMM1 on the main (capture) stream
    k_prevec<<<1, 128>>>(W2, as2, ad2);
    int ng = (N + 63) / 64;
    k_gemm1<<<ng, 256>>>(x, W1, as1, ad1, N);

    // join, then the dependent tail
    cudaStreamWaitEvent(0, evJoin, 0);
    k_agg1<<<(N + 7) / 8, 256>>>(b1, N);
    k_agg2<<<(N + 7) / 8, 256>>>(N);
    k_gemm3<<<ng, 256>>>(W2, b2, N, out);
}